// round 15
// baseline (speedup 1.0000x reference)
#include <cuda_runtime.h>
#include <math.h>

#define C_   32
#define C4_  8
#define D_   48
#define H_   128
#define W_   160
#define HW_  (H_*W_)
#define NV_  4

// padded volume dims: (c4, D+2, H+2, Wp) float4
#define DP_  50
#define HP_  130
#define WP_  168
#define HPW_ (HP_*WP_)
#define CSTRIDE_ (DP_*HPW_)
#define BORDER_PER_PLANE_ 108960

// padded source feature dims (+2 halo each side)
#define WS_  164
#define HS_  132
#define SPLANE_ (HS_*WS_)
#define SRC_BORDER_ 1168     // per-plane border cells = 132*164 - 128*160

typedef unsigned long long u64;

// Scratch (device globals: allocation-free rule)
__device__ float  g_rt[NV_][12];
__device__ float4 g_src4p[NV_*C4_*SPLANE_];   // src feats channel-quads, padded
__device__ float4 g_volp4[C4_*CSTRIDE_];      // padded volume_mean, float4
__device__ float  g_cost[D_*HW_];

// ---- packed f32x2 FMA (Blackwell; identical per-lane rn rounding) ---------
__device__ __forceinline__ u64 fma2_(u64 a, u64 b, u64 c) {
    u64 d; asm("fma.rn.f32x2 %0,%1,%2,%3;" : "=l"(d) : "l"(a), "l"(b), "l"(c)); return d;
}
__device__ __forceinline__ void unpk2(u64 v, float& a, float& b) {
    asm("mov.b64 {%0,%1},%2;" : "=f"(a), "=f"(b) : "l"(v));
}

// ---------------------------------------------------------------------------
// K0: projection algebra (fp64). proj layout: (B=1, V=5, 2, 4, 4).
// ---------------------------------------------------------------------------
__global__ void k_params(const float* __restrict__ proj) {
    if (threadIdx.x != 0 || blockIdx.x != 0) return;

    double Ar[9], ar[3];
    {
        const float* E = proj;
        const float* K = proj + 16;
        for (int i = 0; i < 3; i++) {
            for (int j = 0; j < 3; j++) {
                double s = 0.0;
                for (int k = 0; k < 3; k++) s += (double)K[i*4+k] * (double)E[k*4+j];
                Ar[i*3+j] = s;
            }
            double s = 0.0;
            for (int k = 0; k < 3; k++) s += (double)K[i*4+k] * (double)E[k*4+3];
            ar[i] = s;
        }
    }
    double inv[9];
    double det = Ar[0]*(Ar[4]*Ar[8]-Ar[5]*Ar[7])
               - Ar[1]*(Ar[3]*Ar[8]-Ar[5]*Ar[6])
               + Ar[2]*(Ar[3]*Ar[7]-Ar[4]*Ar[6]);
    double id = 1.0 / det;
    inv[0] = (Ar[4]*Ar[8]-Ar[5]*Ar[7])*id;
    inv[1] = (Ar[2]*Ar[7]-Ar[1]*Ar[8])*id;
    inv[2] = (Ar[1]*Ar[5]-Ar[2]*Ar[4])*id;
    inv[3] = (Ar[5]*Ar[6]-Ar[3]*Ar[8])*id;
    inv[4] = (Ar[0]*Ar[8]-Ar[2]*Ar[6])*id;
    inv[5] = (Ar[2]*Ar[3]-Ar[0]*Ar[5])*id;
    inv[6] = (Ar[3]*Ar[7]-Ar[4]*Ar[6])*id;
    inv[7] = (Ar[1]*Ar[6]-Ar[0]*Ar[7])*id;
    inv[8] = (Ar[0]*Ar[4]-Ar[1]*Ar[3])*id;

    for (int v = 0; v < NV_; v++) {
        const float* E = proj + (v+1)*32;
        const float* K = proj + (v+1)*32 + 16;
        double As[9], as_[3];
        for (int i = 0; i < 3; i++) {
            for (int j = 0; j < 3; j++) {
                double s = 0.0;
                for (int k = 0; k < 3; k++) s += (double)K[i*4+k] * (double)E[k*4+j];
                As[i*3+j] = s;
            }
            double s = 0.0;
            for (int k = 0; k < 3; k++) s += (double)K[i*4+k] * (double)E[k*4+3];
            as_[i] = s;
        }
        double rot[9], tr[3];
        for (int i = 0; i < 3; i++)
            for (int j = 0; j < 3; j++) {
                double s = 0.0;
                for (int k = 0; k < 3; k++) s += As[i*3+k] * inv[k*3+j];
                rot[i*3+j] = s;
            }
        for (int i = 0; i < 3; i++) {
            double s = as_[i];
            for (int k = 0; k < 3; k++) s -= rot[i*3+k] * ar[k];
            tr[i] = s;
        }
        for (int i = 0; i < 9; i++) g_rt[v][i] = (float)rot[i];
        for (int i = 0; i < 3; i++) g_rt[v][9+i] = (float)tr[i];
    }
}

// ---------------------------------------------------------------------------
// Kb: fused border zeroing: padded-src frame + padded-volume border.
// ---------------------------------------------------------------------------
#define NSRCB_ (NV_*C4_*SRC_BORDER_)
__global__ void __launch_bounds__(256) k_borders() {
    int idx = blockIdx.x * 256 + threadIdx.x;
    if (idx < NSRCB_) {
        int plane = idx / SRC_BORDER_;
        int t     = idx % SRC_BORDER_;
        int row, col;
        if (t < 4*WS_) {                       // rows 0,1,130,131 full
            int r = t / WS_;
            row = (r < 2) ? r : (128 + r);
            col = t % WS_;
        } else {
            int q = t - 4*WS_;
            row = 2 + (q >> 2);
            int c = q & 3;
            col = (c < 2) ? c : (W_ + c);      // cols 0,1,162,163
        }
        g_src4p[(size_t)plane*SPLANE_ + row*WS_ + col] = make_float4(0.f,0.f,0.f,0.f);
        return;
    }
    idx -= NSRCB_;
    if (idx >= C4_*BORDER_PER_PLANE_) return;
    int c4 = idx / BORDER_PER_PLANE_;
    int t  = idx % BORDER_PER_PLANE_;
    int dd, yy, xx;
    if (t < 2*HPW_) {                          // d = 0 / 49 full slabs
        int sl = t / HPW_;
        int rr = t % HPW_;
        dd = sl * (DP_-1);
        yy = rr / WP_;
        xx = rr % WP_;
    } else {
        int r = t - 2*HPW_;
        dd = r / 1360 + 1;                     // per-d border = 2*168 + 128*8
        int s = r % 1360;
        if (s < 2*WP_) {                       // y = 0 / 129 rows
            yy = (s / WP_) * (HP_-1);
            xx = s % WP_;
        } else {
            int q = s - 2*WP_;
            yy = (q >> 3) + 1;
            int xc = q & 7;
            xx = (xc == 0) ? 0 : (W_ + xc);    // x=0 and x=161..167
        }
    }
    g_volp4[(size_t)c4*CSTRIDE_ + ((size_t)dd*HP_ + yy)*WP_ + xx]
        = make_float4(0.f, 0.f, 0.f, 0.f);
}

// ---------------------------------------------------------------------------
// Kc: (V,C,H,W) fp32 src -> channel-quad float4 padded. Exact. (ref is
// consumed directly by k_vol from its original layout.)
// ---------------------------------------------------------------------------
__global__ void __launch_bounds__(256) k_cvt(const float* __restrict__ src) {
    int idx = blockIdx.x * 256 + threadIdx.x;
    if (idx >= NV_*C4_*HW_) return;
    int p   = idx % HW_;
    int vc4 = idx / HW_;
    int y   = p / W_;
    int x   = p - y*W_;
    size_t a = (size_t)vc4 * 4 * HW_ + p;
    g_src4p[(size_t)vc4*SPLANE_ + (size_t)(y+2)*WS_ + (x+2)] =
        make_float4(src[a], src[a+HW_], src[a+2*HW_], src[a+3*HW_]);
}

// ---------------------------------------------------------------------------
// K1: build volume_mean (padded float4 layout). Block = 32 x-px x 1 y x 48 d.
// refs staged from original (V,C,H,W) ref layout (no cvt pass needed).
// (round-14 config: measured 150.8 us, L1 at 72.5%)
// ---------------------------------------------------------------------------
__global__ void __launch_bounds__(256, 3) k_vol(const float* __restrict__ ref,
                                                const float* __restrict__ depv) {
    __shared__ float4 refs[NV_][C4_][32];

    const int tx = threadIdx.x;
    const int dg = threadIdx.y;
    const int tid = dg*32 + tx;
    const int x0 = blockIdx.x * 32;
    const int y  = blockIdx.y;
    const int x  = x0 + tx;

    // stage ref quads: gather 4 channel planes per (v,c4,xx)
    for (int i = tid; i < NV_*C4_*32; i += 256) {
        int vc4 = i >> 5;          // v*8 + c4
        int xx  = i & 31;
        size_t a = (size_t)vc4 * 4 * HW_ + y*W_ + x0 + xx;
        ((float4*)refs)[i] = make_float4(ref[a], ref[a+HW_],
                                         ref[a+2*HW_], ref[a+3*HW_]);
    }
    __syncthreads();

    const float fx = (float)x, fy = (float)y;

    for (int i = 0; i < 6; i++) {
        const int d = dg*6 + i;
        const float dep = depv[d];

        int   base[NV_];
        float wx0[NV_], wx1[NV_], wy0[NV_], wy1[NV_];
#pragma unroll
        for (int v = 0; v < NV_; v++) {
            const float* rt = g_rt[v];
            float pz  = (rt[6]*fx + rt[7]*fy + rt[8])*dep + rt[11];
            float ipz = 1.0f / pz;
            float px  = ((rt[0]*fx + rt[1]*fy + rt[2])*dep + rt[9])  * ipz;
            float py  = ((rt[3]*fx + rt[4]*fy + rt[5])*dep + rt[10]) * ipz;

            px = fminf(fmaxf(px, -2.f), (float)W_);
            py = fminf(fmaxf(py, -2.f), (float)H_);

            float x0f = floorf(px), y0f = floorf(py);
            float wx = px - x0f,    wy = py - y0f;

            bool vx0 = (x0f >=  0.f) && (x0f <= (float)(W_-1));
            bool vx1 = (x0f >= -1.f) && (x0f <= (float)(W_-2));
            bool vy0 = (y0f >=  0.f) && (y0f <= (float)(H_-1));
            bool vy1 = (y0f >= -1.f) && (y0f <= (float)(H_-2));

            wx0[v] = vx0 ? (1.f - wx) : 0.f;
            wx1[v] = vx1 ? wx         : 0.f;
            wy0[v] = vy0 ? (1.f - wy) : 0.f;
            wy1[v] = vy1 ? wy         : 0.f;

            base[v] = ((int)y0f + 2)*WS_ + (int)x0f + 2;
        }

        float4* dst = g_volp4 + ((size_t)(d+1)*HP_ + (y+1))*WP_ + (x+1);

        for (int c4 = 0; c4 < C4_; c4++) {
            float a0 = 0.f, a1 = 0.f, a2 = 0.f, a3 = 0.f;
#pragma unroll
            for (int v = 0; v < NV_; v++) {
                const float4* S = g_src4p + (size_t)(v*C4_ + c4)*SPLANE_ + base[v];
                float4 t0 = __ldg(S);
                float4 t1 = __ldg(S + 1);
                float4 t2 = __ldg(S + WS_);
                float4 t3 = __ldg(S + WS_ + 1);
                float r0 = wy0[v]*(wx0[v]*t0.x + wx1[v]*t1.x) + wy1[v]*(wx0[v]*t2.x + wx1[v]*t3.x);
                float r1 = wy0[v]*(wx0[v]*t0.y + wx1[v]*t1.y) + wy1[v]*(wx0[v]*t2.y + wx1[v]*t3.y);
                float r2 = wy0[v]*(wx0[v]*t0.z + wx1[v]*t1.z) + wy1[v]*(wx0[v]*t2.z + wx1[v]*t3.z);
                float r3 = wy0[v]*(wx0[v]*t0.w + wx1[v]*t1.w) + wy1[v]*(wx0[v]*t2.w + wx1[v]*t3.w);
                float4 rf = refs[v][c4][tx];
                a0 += rf.x * r0;
                a1 += rf.y * r1;
                a2 += rf.z * r2;
                a3 += rf.w * r3;
            }
            dst[(size_t)c4*CSTRIDE_] =
                make_float4(a0*0.25f, a1*0.25f, a2*0.25f, a3*0.25f);
        }
    }
}

// ---------------------------------------------------------------------------
// K2: 3x3x3 conv via padded float4 volume, d-tile 4, block 32x4 (128 thr).
// Thread owns 2 y x 4 d = 8 outputs. (round-13 config: measured ~41 us)
// ---------------------------------------------------------------------------
__global__ void __launch_bounds__(128) k_conv(const float* __restrict__ wreg) {
    __shared__ float4 tile[2040];        // [6 d][10 y][34 x]
    __shared__ float4 wsh4[C4_*27];      // 4-channel packed weights

    const int tx = threadIdx.x, ty = threadIdx.y;   // ty in 0..3
    const int tid = ty*32 + tx;
    const int x0 = blockIdx.x*32, y0 = blockIdx.y*8, d0 = blockIdx.z*4;

    for (int i = tid; i < C4_*27; i += 128) {
        int c4 = i / 27, t = i % 27;
        wsh4[i] = make_float4(wreg[(4*c4  )*27 + t], wreg[(4*c4+1)*27 + t],
                              wreg[(4*c4+2)*27 + t], wreg[(4*c4+3)*27 + t]);
    }

    int gOff[16];
#pragma unroll
    for (int k = 0; k < 16; k++) {
        int i = tid + k*128;
        if (i < 2040) {
            int dd = i / 340;
            int r  = i - dd*340;
            int yy = r / 34;
            int xx = r - yy*34;
            gOff[k] = (dd*HP_ + yy)*WP_ + xx;
        } else gOff[k] = 0;
    }
    const size_t base0 = ((size_t)d0*HP_ + y0)*WP_ + x0;

    // accumulators: [yl][j] packed channel pairs
    u64 a01[2][4], a23[2][4];
#pragma unroll
    for (int yl = 0; yl < 2; yl++)
#pragma unroll
        for (int j = 0; j < 4; j++) { a01[yl][j] = 0ULL; a23[yl][j] = 0ULL; }

    for (int c4 = 0; c4 < C4_; c4++) {
        __syncthreads();
        const float4* p = g_volp4 + (size_t)c4*CSTRIDE_ + base0;
#pragma unroll
        for (int k = 0; k < 15; k++)
            tile[tid + k*128] = __ldg(p + gOff[k]);
        if (tid < 2040 - 15*128)
            tile[tid + 15*128] = __ldg(p + gOff[15]);
        __syncthreads();

#pragma unroll
        for (int dx = 0; dx < 3; dx++) {
#pragma unroll
            for (int r = 0; r < 4; r++) {          // tile row = ty*2 + r
                ulonglong2 col[6];
#pragma unroll
                for (int k = 0; k < 6; k++)
                    col[k] = *reinterpret_cast<const ulonglong2*>(
                                 &tile[k*340 + (ty*2 + r)*34 + tx + dx]);
#pragma unroll
                for (int yl = 0; yl < 2; yl++) {
                    int dy = r - yl;
                    if (dy < 0 || dy > 2) continue;   // compile-time after unroll
#pragma unroll
                    for (int dz = 0; dz < 3; dz++) {
                        ulonglong2 w = *reinterpret_cast<const ulonglong2*>(
                                           &wsh4[c4*27 + dz*9 + dy*3 + dx]);
#pragma unroll
                        for (int j = 0; j < 4; j++) {
                            a01[yl][j] = fma2_(w.x, col[j + dz].x, a01[yl][j]);
                            a23[yl][j] = fma2_(w.y, col[j + dz].y, a23[yl][j]);
                        }
                    }
                }
            }
        }
    }

#pragma unroll
    for (int yl = 0; yl < 2; yl++)
#pragma unroll
        for (int j = 0; j < 4; j++) {
            float f0, f1, f2, f3;
            unpk2(a01[yl][j], f0, f1);
            unpk2(a23[yl][j], f2, f3);
            g_cost[(size_t)(d0 + j)*HW_ + (y0 + ty*2 + yl)*W_ + (x0 + tx)]
                = (f0 + f1) + (f2 + f3);
        }
}

// ---------------------------------------------------------------------------
// K3: softmax over D + expected depth + confidence. Cost cached in registers.
// ---------------------------------------------------------------------------
__global__ void __launch_bounds__(W_) k_post(const float* __restrict__ depv,
                                             float* __restrict__ out) {
    const int x = threadIdx.x;
    const int y = blockIdx.x;
    const int pix = y*W_ + x;

    float cv[D_];
    float m = -1e30f;
#pragma unroll
    for (int d = 0; d < D_; d++) {
        cv[d] = g_cost[(size_t)d*HW_ + pix];
        m = fmaxf(m, cv[d]);
    }

    float s = 0.f, sd = 0.f, sdep = 0.f;
#pragma unroll
    for (int d = 0; d < D_; d++) {
        float e = expf(cv[d] - m);
        s    += e;
        sd   += e * (float)d;
        sdep += e * depv[d];
    }
    float invs = 1.f / s;
    out[pix] = sdep * invs;

    int idx = (int)(sd * invs);
    idx = min(max(idx, 0), D_-1);

    float cw = 0.f;
#pragma unroll
    for (int t = -1; t <= 2; t++) {
        int dd = idx + t;
        if (dd >= 0 && dd < D_)
            cw += expf(cv[dd] - m);
    }
    out[HW_ + pix] = cw * invs;
}

// ---------------------------------------------------------------------------
extern "C" void kernel_launch(void* const* d_in, const int* in_sizes, int n_in,
                              void* d_out, int out_size) {
    const float* ref  = (const float*)d_in[0];
    const float* src  = (const float*)d_in[1];
    const float* proj = (const float*)d_in[2];
    const float* depv = (const float*)d_in[3];

    const float* wreg = (const float*)d_in[n_in - 1];
    for (int i = 4; i < n_in; i++)
        if (in_sizes[i] == C_*27) { wreg = (const float*)d_in[i]; break; }

    float* out = (float*)d_out;

    int nborder = NSRCB_ + C4_*BORDER_PER_PLANE_;
    k_params<<<1, 32>>>(proj);
    k_borders<<<(nborder + 255)/256, 256>>>();
    k_cvt<<<(NV_*C4_*HW_ + 255)/256, 256>>>(src);
    k_vol<<<dim3(W_/32, H_), dim3(32, 8)>>>(ref, depv);
    k_conv<<<dim3(W_/32, H_/8, D_/4), dim3(32, 4)>>>(wreg);
    k_post<<<H_, W_>>>(depv, out);
}

// round 16
// speedup vs baseline: 1.5841x; 1.5841x over previous
#include <cuda_runtime.h>
#include <math.h>

#define C_   32
#define C4_  8
#define D_   48
#define H_   128
#define W_   160
#define HW_  (H_*W_)
#define NV_  4

// padded volume dims: (c4, D+2, H+2, Wp) float4
#define DP_  50
#define HP_  130
#define WP_  168
#define HPW_ (HP_*WP_)
#define CSTRIDE_ (DP_*HPW_)
#define BORDER_PER_PLANE_ 108960

// padded source feature dims (+2 halo each side)
#define WS_  164
#define HS_  132
#define SPLANE_ (HS_*WS_)
#define SRC_BORDER_ 1168     // per-plane border cells = 132*164 - 128*160

typedef unsigned long long u64;

// Scratch (device globals: allocation-free rule)
__device__ float  g_rt[NV_][12];
__device__ float4 g_src4p[NV_*C4_*SPLANE_];   // src feats channel-quads, padded
__device__ float4 g_volp4[C4_*CSTRIDE_];      // padded volume_mean, float4
__device__ float  g_cost[D_*HW_];

// ---- packed f32x2 FMA (Blackwell; identical per-lane rn rounding) ---------
__device__ __forceinline__ u64 fma2_(u64 a, u64 b, u64 c) {
    u64 d; asm("fma.rn.f32x2 %0,%1,%2,%3;" : "=l"(d) : "l"(a), "l"(b), "l"(c)); return d;
}
__device__ __forceinline__ void unpk2(u64 v, float& a, float& b) {
    asm("mov.b64 {%0,%1},%2;" : "=f"(a), "=f"(b) : "l"(v));
}

// ---------------------------------------------------------------------------
// K0: projection algebra (fp64). proj layout: (B=1, V=5, 2, 4, 4).
// ---------------------------------------------------------------------------
__global__ void k_params(const float* __restrict__ proj) {
    if (threadIdx.x != 0 || blockIdx.x != 0) return;

    double Ar[9], ar[3];
    {
        const float* E = proj;
        const float* K = proj + 16;
        for (int i = 0; i < 3; i++) {
            for (int j = 0; j < 3; j++) {
                double s = 0.0;
                for (int k = 0; k < 3; k++) s += (double)K[i*4+k] * (double)E[k*4+j];
                Ar[i*3+j] = s;
            }
            double s = 0.0;
            for (int k = 0; k < 3; k++) s += (double)K[i*4+k] * (double)E[k*4+3];
            ar[i] = s;
        }
    }
    double inv[9];
    double det = Ar[0]*(Ar[4]*Ar[8]-Ar[5]*Ar[7])
               - Ar[1]*(Ar[3]*Ar[8]-Ar[5]*Ar[6])
               + Ar[2]*(Ar[3]*Ar[7]-Ar[4]*Ar[6]);
    double id = 1.0 / det;
    inv[0] = (Ar[4]*Ar[8]-Ar[5]*Ar[7])*id;
    inv[1] = (Ar[2]*Ar[7]-Ar[1]*Ar[8])*id;
    inv[2] = (Ar[1]*Ar[5]-Ar[2]*Ar[4])*id;
    inv[3] = (Ar[5]*Ar[6]-Ar[3]*Ar[8])*id;
    inv[4] = (Ar[0]*Ar[8]-Ar[2]*Ar[6])*id;
    inv[5] = (Ar[2]*Ar[3]-Ar[0]*Ar[5])*id;
    inv[6] = (Ar[3]*Ar[7]-Ar[4]*Ar[6])*id;
    inv[7] = (Ar[1]*Ar[6]-Ar[0]*Ar[7])*id;
    inv[8] = (Ar[0]*Ar[4]-Ar[1]*Ar[3])*id;

    for (int v = 0; v < NV_; v++) {
        const float* E = proj + (v+1)*32;
        const float* K = proj + (v+1)*32 + 16;
        double As[9], as_[3];
        for (int i = 0; i < 3; i++) {
            for (int j = 0; j < 3; j++) {
                double s = 0.0;
                for (int k = 0; k < 3; k++) s += (double)K[i*4+k] * (double)E[k*4+j];
                As[i*3+j] = s;
            }
            double s = 0.0;
            for (int k = 0; k < 3; k++) s += (double)K[i*4+k] * (double)E[k*4+3];
            as_[i] = s;
        }
        double rot[9], tr[3];
        for (int i = 0; i < 3; i++)
            for (int j = 0; j < 3; j++) {
                double s = 0.0;
                for (int k = 0; k < 3; k++) s += As[i*3+k] * inv[k*3+j];
                rot[i*3+j] = s;
            }
        for (int i = 0; i < 3; i++) {
            double s = as_[i];
            for (int k = 0; k < 3; k++) s -= rot[i*3+k] * ar[k];
            tr[i] = s;
        }
        for (int i = 0; i < 9; i++) g_rt[v][i] = (float)rot[i];
        for (int i = 0; i < 3; i++) g_rt[v][9+i] = (float)tr[i];
    }
}

// ---------------------------------------------------------------------------
// Kb: fused border zeroing: padded-src frame + padded-volume border.
// ---------------------------------------------------------------------------
#define NSRCB_ (NV_*C4_*SRC_BORDER_)
__global__ void __launch_bounds__(256) k_borders() {
    int idx = blockIdx.x * 256 + threadIdx.x;
    if (idx < NSRCB_) {
        int plane = idx / SRC_BORDER_;
        int t     = idx % SRC_BORDER_;
        int row, col;
        if (t < 4*WS_) {                       // rows 0,1,130,131 full
            int r = t / WS_;
            row = (r < 2) ? r : (128 + r);
            col = t % WS_;
        } else {
            int q = t - 4*WS_;
            row = 2 + (q >> 2);
            int c = q & 3;
            col = (c < 2) ? c : (W_ + c);      // cols 0,1,162,163
        }
        g_src4p[(size_t)plane*SPLANE_ + row*WS_ + col] = make_float4(0.f,0.f,0.f,0.f);
        return;
    }
    idx -= NSRCB_;
    if (idx >= C4_*BORDER_PER_PLANE_) return;
    int c4 = idx / BORDER_PER_PLANE_;
    int t  = idx % BORDER_PER_PLANE_;
    int dd, yy, xx;
    if (t < 2*HPW_) {                          // d = 0 / 49 full slabs
        int sl = t / HPW_;
        int rr = t % HPW_;
        dd = sl * (DP_-1);
        yy = rr / WP_;
        xx = rr % WP_;
    } else {
        int r = t - 2*HPW_;
        dd = r / 1360 + 1;                     // per-d border = 2*168 + 128*8
        int s = r % 1360;
        if (s < 2*WP_) {                       // y = 0 / 129 rows
            yy = (s / WP_) * (HP_-1);
            xx = s % WP_;
        } else {
            int q = s - 2*WP_;
            yy = (q >> 3) + 1;
            int xc = q & 7;
            xx = (xc == 0) ? 0 : (W_ + xc);    // x=0 and x=161..167
        }
    }
    g_volp4[(size_t)c4*CSTRIDE_ + ((size_t)dd*HP_ + yy)*WP_ + xx]
        = make_float4(0.f, 0.f, 0.f, 0.f);
}

// ---------------------------------------------------------------------------
// Kc: (V,C,H,W) fp32 src -> channel-quad float4 padded. Exact. (ref is
// consumed directly by k_vol from its original layout.)
// ---------------------------------------------------------------------------
__global__ void __launch_bounds__(256) k_cvt(const float* __restrict__ src) {
    int idx = blockIdx.x * 256 + threadIdx.x;
    if (idx >= NV_*C4_*HW_) return;
    int p   = idx % HW_;
    int vc4 = idx / HW_;
    int y   = p / W_;
    int x   = p - y*W_;
    size_t a = (size_t)vc4 * 4 * HW_ + p;
    g_src4p[(size_t)vc4*SPLANE_ + (size_t)(y+2)*WS_ + (x+2)] =
        make_float4(src[a], src[a+HW_], src[a+2*HW_], src[a+3*HW_]);
}

// ---------------------------------------------------------------------------
// K1: build volume_mean (padded float4 layout). Block = 32 x-px x 1 y x 48 d.
// refs staged from original (V,C,H,W) ref layout (no cvt pass needed).
// (measured 150.8 us @ 626 GB/s on a fast-clock run)
// ---------------------------------------------------------------------------
__global__ void __launch_bounds__(256, 3) k_vol(const float* __restrict__ ref,
                                                const float* __restrict__ depv) {
    __shared__ float4 refs[NV_][C4_][32];

    const int tx = threadIdx.x;
    const int dg = threadIdx.y;
    const int tid = dg*32 + tx;
    const int x0 = blockIdx.x * 32;
    const int y  = blockIdx.y;
    const int x  = x0 + tx;

    // stage ref quads: gather 4 channel planes per (v,c4,xx)
    for (int i = tid; i < NV_*C4_*32; i += 256) {
        int vc4 = i >> 5;          // v*8 + c4
        int xx  = i & 31;
        size_t a = (size_t)vc4 * 4 * HW_ + y*W_ + x0 + xx;
        ((float4*)refs)[i] = make_float4(ref[a], ref[a+HW_],
                                         ref[a+2*HW_], ref[a+3*HW_]);
    }
    __syncthreads();

    const float fx = (float)x, fy = (float)y;

    for (int i = 0; i < 6; i++) {
        const int d = dg*6 + i;
        const float dep = depv[d];

        int   base[NV_];
        float wx0[NV_], wx1[NV_], wy0[NV_], wy1[NV_];
#pragma unroll
        for (int v = 0; v < NV_; v++) {
            const float* rt = g_rt[v];
            float pz  = (rt[6]*fx + rt[7]*fy + rt[8])*dep + rt[11];
            float ipz = 1.0f / pz;
            float px  = ((rt[0]*fx + rt[1]*fy + rt[2])*dep + rt[9])  * ipz;
            float py  = ((rt[3]*fx + rt[4]*fy + rt[5])*dep + rt[10]) * ipz;

            px = fminf(fmaxf(px, -2.f), (float)W_);
            py = fminf(fmaxf(py, -2.f), (float)H_);

            float x0f = floorf(px), y0f = floorf(py);
            float wx = px - x0f,    wy = py - y0f;

            bool vx0 = (x0f >=  0.f) && (x0f <= (float)(W_-1));
            bool vx1 = (x0f >= -1.f) && (x0f <= (float)(W_-2));
            bool vy0 = (y0f >=  0.f) && (y0f <= (float)(H_-1));
            bool vy1 = (y0f >= -1.f) && (y0f <= (float)(H_-2));

            wx0[v] = vx0 ? (1.f - wx) : 0.f;
            wx1[v] = vx1 ? wx         : 0.f;
            wy0[v] = vy0 ? (1.f - wy) : 0.f;
            wy1[v] = vy1 ? wy         : 0.f;

            base[v] = ((int)y0f + 2)*WS_ + (int)x0f + 2;
        }

        float4* dst = g_volp4 + ((size_t)(d+1)*HP_ + (y+1))*WP_ + (x+1);

        for (int c4 = 0; c4 < C4_; c4++) {
            float a0 = 0.f, a1 = 0.f, a2 = 0.f, a3 = 0.f;
#pragma unroll
            for (int v = 0; v < NV_; v++) {
                const float4* S = g_src4p + (size_t)(v*C4_ + c4)*SPLANE_ + base[v];
                float4 t0 = __ldg(S);
                float4 t1 = __ldg(S + 1);
                float4 t2 = __ldg(S + WS_);
                float4 t3 = __ldg(S + WS_ + 1);
                float r0 = wy0[v]*(wx0[v]*t0.x + wx1[v]*t1.x) + wy1[v]*(wx0[v]*t2.x + wx1[v]*t3.x);
                float r1 = wy0[v]*(wx0[v]*t0.y + wx1[v]*t1.y) + wy1[v]*(wx0[v]*t2.y + wx1[v]*t3.y);
                float r2 = wy0[v]*(wx0[v]*t0.z + wx1[v]*t1.z) + wy1[v]*(wx0[v]*t2.z + wx1[v]*t3.z);
                float r3 = wy0[v]*(wx0[v]*t0.w + wx1[v]*t1.w) + wy1[v]*(wx0[v]*t2.w + wx1[v]*t3.w);
                float4 rf = refs[v][c4][tx];
                a0 += rf.x * r0;
                a1 += rf.y * r1;
                a2 += rf.z * r2;
                a3 += rf.w * r3;
            }
            dst[(size_t)c4*CSTRIDE_] =
                make_float4(a0*0.25f, a1*0.25f, a2*0.25f, a3*0.25f);
        }
    }
}

// ---------------------------------------------------------------------------
// K2: 3x3x3 conv via padded float4 volume, d-tile 4, block 32x4 (128 thr).
// Thread owns 2 y x 4 d = 8 outputs. (round-13 config: measured ~41 us)
// ---------------------------------------------------------------------------
__global__ void __launch_bounds__(128) k_conv(const float* __restrict__ wreg) {
    __shared__ float4 tile[2040];        // [6 d][10 y][34 x]
    __shared__ float4 wsh4[C4_*27];      // 4-channel packed weights

    const int tx = threadIdx.x, ty = threadIdx.y;   // ty in 0..3
    const int tid = ty*32 + tx;
    const int x0 = blockIdx.x*32, y0 = blockIdx.y*8, d0 = blockIdx.z*4;

    for (int i = tid; i < C4_*27; i += 128) {
        int c4 = i / 27, t = i % 27;
        wsh4[i] = make_float4(wreg[(4*c4  )*27 + t], wreg[(4*c4+1)*27 + t],
                              wreg[(4*c4+2)*27 + t], wreg[(4*c4+3)*27 + t]);
    }

    int gOff[16];
#pragma unroll
    for (int k = 0; k < 16; k++) {
        int i = tid + k*128;
        if (i < 2040) {
            int dd = i / 340;
            int r  = i - dd*340;
            int yy = r / 34;
            int xx = r - yy*34;
            gOff[k] = (dd*HP_ + yy)*WP_ + xx;
        } else gOff[k] = 0;
    }
    const size_t base0 = ((size_t)d0*HP_ + y0)*WP_ + x0;

    // accumulators: [yl][j] packed channel pairs
    u64 a01[2][4], a23[2][4];
#pragma unroll
    for (int yl = 0; yl < 2; yl++)
#pragma unroll
        for (int j = 0; j < 4; j++) { a01[yl][j] = 0ULL; a23[yl][j] = 0ULL; }

    for (int c4 = 0; c4 < C4_; c4++) {
        __syncthreads();
        const float4* p = g_volp4 + (size_t)c4*CSTRIDE_ + base0;
#pragma unroll
        for (int k = 0; k < 15; k++)
            tile[tid + k*128] = __ldg(p + gOff[k]);
        if (tid < 2040 - 15*128)
            tile[tid + 15*128] = __ldg(p + gOff[15]);
        __syncthreads();

#pragma unroll
        for (int dx = 0; dx < 3; dx++) {
#pragma unroll
            for (int r = 0; r < 4; r++) {          // tile row = ty*2 + r
                ulonglong2 col[6];
#pragma unroll
                for (int k = 0; k < 6; k++)
                    col[k] = *reinterpret_cast<const ulonglong2*>(
                                 &tile[k*340 + (ty*2 + r)*34 + tx + dx]);
#pragma unroll
                for (int yl = 0; yl < 2; yl++) {
                    int dy = r - yl;
                    if (dy < 0 || dy > 2) continue;   // compile-time after unroll
#pragma unroll
                    for (int dz = 0; dz < 3; dz++) {
                        ulonglong2 w = *reinterpret_cast<const ulonglong2*>(
                                           &wsh4[c4*27 + dz*9 + dy*3 + dx]);
#pragma unroll
                        for (int j = 0; j < 4; j++) {
                            a01[yl][j] = fma2_(w.x, col[j + dz].x, a01[yl][j]);
                            a23[yl][j] = fma2_(w.y, col[j + dz].y, a23[yl][j]);
                        }
                    }
                }
            }
        }
    }

#pragma unroll
    for (int yl = 0; yl < 2; yl++)
#pragma unroll
        for (int j = 0; j < 4; j++) {
            float f0, f1, f2, f3;
            unpk2(a01[yl][j], f0, f1);
            unpk2(a23[yl][j], f2, f3);
            g_cost[(size_t)(d0 + j)*HW_ + (y0 + ty*2 + yl)*W_ + (x0 + tx)]
                = (f0 + f1) + (f2 + f3);
        }
}

// ---------------------------------------------------------------------------
// K3: softmax over D + expected depth + confidence. Cost cached in registers.
// ---------------------------------------------------------------------------
__global__ void __launch_bounds__(W_) k_post(const float* __restrict__ depv,
                                             float* __restrict__ out) {
    const int x = threadIdx.x;
    const int y = blockIdx.x;
    const int pix = y*W_ + x;

    float cv[D_];
    float m = -1e30f;
#pragma unroll
    for (int d = 0; d < D_; d++) {
        cv[d] = g_cost[(size_t)d*HW_ + pix];
        m = fmaxf(m, cv[d]);
    }

    float s = 0.f, sd = 0.f, sdep = 0.f;
#pragma unroll
    for (int d = 0; d < D_; d++) {
        float e = expf(cv[d] - m);
        s    += e;
        sd   += e * (float)d;
        sdep += e * depv[d];
    }
    float invs = 1.f / s;
    out[pix] = sdep * invs;

    int idx = (int)(sd * invs);
    idx = min(max(idx, 0), D_-1);

    float cw = 0.f;
#pragma unroll
    for (int t = -1; t <= 2; t++) {
        int dd = idx + t;
        if (dd >= 0 && dd < D_)
            cw += expf(cv[dd] - m);
    }
    out[HW_ + pix] = cw * invs;
}

// ---------------------------------------------------------------------------
extern "C" void kernel_launch(void* const* d_in, const int* in_sizes, int n_in,
                              void* d_out, int out_size) {
    const float* ref  = (const float*)d_in[0];
    const float* src  = (const float*)d_in[1];
    const float* proj = (const float*)d_in[2];
    const float* depv = (const float*)d_in[3];

    const float* wreg = (const float*)d_in[n_in - 1];
    for (int i = 4; i < n_in; i++)
        if (in_sizes[i] == C_*27) { wreg = (const float*)d_in[i]; break; }

    float* out = (float*)d_out;

    int nborder = NSRCB_ + C4_*BORDER_PER_PLANE_;
    k_params<<<1, 32>>>(proj);
    k_borders<<<(nborder + 255)/256, 256>>>();
    k_cvt<<<(NV_*C4_*HW_ + 255)/256, 256>>>(src);
    k_vol<<<dim3(W_/32, H_), dim3(32, 8)>>>(ref, depv);
    k_conv<<<dim3(W_/32, H_/8, D_/4), dim3(32, 4)>>>(wreg);
    k_post<<<H_, W_>>>(depv, out);
}